// round 15
// baseline (speedup 1.0000x reference)
#include <cuda_runtime.h>
#include <cuda_bf16.h>
#include <math.h>

#define HDIM 512
#define NDIM 32
#define LLEN 4096
#define LF   2049   // LLEN/2 + 1

// ---------------- packed f32x2 + fast-rcp helpers ---------------------------
typedef unsigned long long u64;
__device__ __forceinline__ u64 pk(float lo, float hi) {
    u64 r; asm("mov.b64 %0,{%1,%2};" : "=l"(r) : "f"(lo), "f"(hi)); return r;
}
__device__ __forceinline__ void upk(float& lo, float& hi, u64 v) {
    asm("mov.b64 {%0,%1},%2;" : "=f"(lo), "=f"(hi) : "l"(v));
}
__device__ __forceinline__ u64 f2add(u64 a, u64 b) {
    u64 d; asm("add.rn.f32x2 %0,%1,%2;" : "=l"(d) : "l"(a), "l"(b)); return d;
}
__device__ __forceinline__ u64 f2mul(u64 a, u64 b) {
    u64 d; asm("mul.rn.f32x2 %0,%1,%2;" : "=l"(d) : "l"(a), "l"(b)); return d;
}
__device__ __forceinline__ u64 f2fma(u64 a, u64 b, u64 c) {
    u64 d; asm("fma.rn.f32x2 %0,%1,%2,%3;" : "=l"(d) : "l"(a), "l"(b), "l"(c)); return d;
}
__device__ __forceinline__ float frcp(float x) {        // single MUFU.RCP
    float r; asm("rcp.approx.f32 %0,%1;" : "=f"(r) : "f"(x)); return r;
}

#define IX(i) ((i) ^ (((i) >> 4) & 15))   // X / TW swizzle
#define SK(i) ((i) ^ (((i) >> 4) & 15))   // KF swizzle (range < 2064)

__device__ __forceinline__ float2 cmul(float2 a, float2 b) {
    return make_float2(a.x * b.x - a.y * b.y, a.x * b.y + a.y * b.x);
}
__device__ __forceinline__ void bfly4(float2& x0, float2& x1, float2& x2, float2& x3,
                                      float2 w1, float2 w2, float2 w3) {
    const float2 t0 = x0, t1 = cmul(x1, w1), t2 = cmul(x2, w2), t3 = cmul(x3, w3);
    const float ax = t0.x + t2.x, ay = t0.y + t2.y;
    const float bx = t0.x - t2.x, by = t0.y - t2.y;
    const float cx = t1.x + t3.x, cy = t1.y + t3.y;
    const float dx = -(t1.y - t3.y), dy = t1.x - t3.x;
    x0 = make_float2(ax + cx, ay + cy);
    x1 = make_float2(bx + dx, by + dy);
    x2 = make_float2(ax - cx, ay - cy);
    x3 = make_float2(bx - dx, by - dy);
}
__device__ __forceinline__ void bfly4u(float2 t0, float2 t1, float2 t2, float2 t3,
                                       float2& y0, float2& y1, float2& y2, float2& y3) {
    const float ax = t0.x + t2.x, ay = t0.y + t2.y;
    const float bx = t0.x - t2.x, by = t0.y - t2.y;
    const float cx = t1.x + t3.x, cy = t1.y + t3.y;
    const float dx = -(t1.y - t3.y), dy = t1.x - t3.x;
    y0 = make_float2(ax + cx, ay + cy);
    y1 = make_float2(bx + dx, by + dy);
    y2 = make_float2(ax - cx, ay - cy);
    y3 = make_float2(bx - dx, by - dy);
}

// dynamic smem layout (float2 units): X[0..4095], TW[4096..5119], KF[5120..7183]
#define SMEM_F2_TOTAL 7184

__global__ void __launch_bounds__(256, 3) fused_kernel(
                              const float* __restrict__ w_re, const float* __restrict__ w_im,
                              const float* __restrict__ p_re, const float* __restrict__ p_im,
                              const float* __restrict__ B_re, const float* __restrict__ B_im,
                              const float* __restrict__ C_re, const float* __restrict__ C_im,
                              const float* __restrict__ log_dt,
                              float* __restrict__ out) {
    extern __shared__ float2 smem[];
    float2* X  = smem;            // IX swizzled
    float2* TW = smem + 4096;     // IX swizzled
    float2* KF = smem + 5120;     // SK swizzled

    __shared__ u64 s_MM[NDIM], s_cc[NDIM];
    __shared__ u64 s_ab0[NDIM], s_ab1[NDIM], s_ab2[NDIM], s_ab3[NDIM];
    __shared__ float s_ny[NDIM];

    const int h   = blockIdx.x;
    const int tid = threadIdx.x;

    // ---- twiddle table (W^j = e^{+2*pi*i*j/4096}) --------------------------
    #pragma unroll
    for (int q = 0; q < 4; q++) {
        const int j = tid + 256 * q;
        float s, c;
        sincosf((float)j * (float)(2.0 * M_PI / (double)LLEN), &s, &c);
        TW[IX(j)] = make_float2(c, s);
    }

    // ---- per-head tables ---------------------------------------------------
    const float dt = expf(log_dt[h]);
    if (tid < NDIM) {
        const int idx = h * NDIM + tid;
        const float wr = w_re[idx] * dt, wi = w_im[idx] * dt;
        const float M = wr * wr + wi * wi, c = -2.0f * wr;
        s_MM[tid] = pk(M, M);
        s_cc[tid] = pk(c, c);
        const float br = B_re[idx], bi = B_im[idx];
        const float cr = C_re[idx], ci = C_im[idx];
        const float pr = p_re[idx], pi = p_im[idx];
        const float v00r = dt * (br * cr - bi * ci), v00i = dt * (br * ci + bi * cr);
        const float v01r = dt * (br * pr + bi * pi), v01i = dt * (bi * pr - br * pi);
        const float v10r = dt * (pr * cr - pi * ci), v10i = dt * (pr * ci + pi * cr);
        const float v11r = dt * (pr * pr + pi * pi);
        s_ab0[tid] = pk(-2.f * (v00r * wr + v00i * wi), 2.f * v00r);
        s_ab1[tid] = pk(-2.f * (v01r * wr + v01i * wi), 2.f * v01r);
        s_ab2[tid] = pk(-2.f * (v10r * wr + v10i * wi), 2.f * v10r);
        s_ab3[tid] = pk(-2.f * (v11r * wr),             2.f * v11r);
        s_ny[tid]  = v00r;
    }
    __syncthreads();

    // ---- cauchy phase: FOUR chunks of 2 l-values (8 accumulators each) -----
    #pragma unroll 1
    for (int cch = 0; cch < 4; cch++) {
        const int l0 = cch * 512 + tid;   // l = l0, l0 + 256

        const float y0 = 2.0f * tanf((float)l0 * (float)(M_PI / (double)LLEN));
        const float y1 = 2.0f * tanf((float)(l0 + 256) * (float)(M_PI / (double)LLEN));
        const u64 yP   = pk(y0, y1);
        const u64 ny2P = pk(-y0 * y0, -y1 * y1);
        float yv[2]; yv[0] = y0; yv[1] = y1;

        u64 a1_00 = 0, a2_00 = 0, a1_01 = 0, a2_01 = 0;
        u64 a1_10 = 0, a2_10 = 0, a1_11 = 0, a2_11 = 0;

        #pragma unroll 4
        for (int n = 0; n < NDIM; n++) {
            const u64 DrP  = f2add(s_MM[n], ny2P);
            const u64 DiP  = f2mul(s_cc[n], yP);
            const u64 denP = f2fma(DiP, DiP, f2mul(DrP, DrP));
            float de0, de1; upk(de0, de1, denP);
            const u64 invP = pk(frcp(de0), frcp(de1));
            const u64 grP  = f2mul(DrP, invP);
            const u64 hP   = f2mul(DiP, invP);      // h = -gi
            float gr0, gr1; upk(gr0, gr1, grP);
            float h0,  h1;  upk(h0,  h1,  hP);
            const u64 ggA = pk(gr0, gr0), ggB = pk(gr1, gr1);
            const u64 hhA = pk(h0, h0),   hhB = pk(h1, h1);
            // lane A accumulators hold l0 terms in .lo? No: accumulator lanes
            // are (alpha, beta) rows; chunk has ONE l-pair so we alternate:
            // use ggA/hhA for lane-l0 accumulation into a*_XX lane structure.
            // a1 = sum(ab * gr_l), a2 = sum(ab * h_l) with separate regs per l:
            a1_00 = f2fma(s_ab0[n], ggA, a1_00);  a2_00 = f2fma(s_ab0[n], hhA, a2_00);
            a1_01 = f2fma(s_ab1[n], ggA, a1_01);  a2_01 = f2fma(s_ab1[n], hhA, a2_01);
            a1_10 = f2fma(s_ab2[n], ggA, a1_10);  a2_10 = f2fma(s_ab2[n], hhA, a2_10);
            a1_11 = f2fma(s_ab3[n], ggA, a1_11);  a2_11 = f2fma(s_ab3[n], hhA, a2_11);
            // second l of the pair reuses same accumulators? NO — needs its own.
            // (handled below via second accumulator set)
            (void)ggB; (void)hhB;
        }
        // NOTE: the above covers only lane l0; re-run for l1 would double cost.
        // Instead we keep TWO accumulator sets inline (see b-set below).
        // --- second pass for l1 (kept separate to cap register pressure) ---
        u64 b1_00 = 0, b2_00 = 0, b1_01 = 0, b2_01 = 0;
        u64 b1_10 = 0, b2_10 = 0, b1_11 = 0, b2_11 = 0;
        #pragma unroll 4
        for (int n = 0; n < NDIM; n++) {
            const u64 DrP  = f2add(s_MM[n], ny2P);
            const u64 DiP  = f2mul(s_cc[n], yP);
            const u64 denP = f2fma(DiP, DiP, f2mul(DrP, DrP));
            float de0, de1; upk(de0, de1, denP);
            const u64 invP = pk(frcp(de0), frcp(de1));
            const u64 grP  = f2mul(DrP, invP);
            const u64 hP   = f2mul(DiP, invP);
            float gr0, gr1; upk(gr0, gr1, grP);
            float h0,  h1;  upk(h0,  h1,  hP);
            const u64 ggB = pk(gr1, gr1), hhB = pk(h1, h1);
            b1_00 = f2fma(s_ab0[n], ggB, b1_00);  b2_00 = f2fma(s_ab0[n], hhB, b2_00);
            b1_01 = f2fma(s_ab1[n], ggB, b1_01);  b2_01 = f2fma(s_ab1[n], hhB, b2_01);
            b1_10 = f2fma(s_ab2[n], ggB, b1_10);  b2_10 = f2fma(s_ab2[n], hhB, b2_10);
            b1_11 = f2fma(s_ab3[n], ggB, b1_11);  b2_11 = f2fma(s_ab3[n], hhB, b2_11);
        }

        #pragma unroll
        for (int j = 0; j < 2; j++) {
            const float y = yv[j];
            const u64 A00 = j ? b1_00 : a1_00, Q00 = j ? b2_00 : a2_00;
            const u64 A01 = j ? b1_01 : a1_01, Q01 = j ? b2_01 : a2_01;
            const u64 A10 = j ? b1_10 : a1_10, Q10 = j ? b2_10 : a2_10;
            const u64 A11 = j ? b1_11 : a1_11, Q11 = j ? b2_11 : a2_11;
            float g00, b00, i00, q00; upk(g00, b00, A00); upk(i00, q00, Q00);
            float g01, b01, i01, q01; upk(g01, b01, A01); upk(i01, q01, Q01);
            float g10, b10, i10, q10; upk(g10, b10, A10); upk(i10, q10, Q10);
            float g11, b11, i11, q11; upk(g11, b11, A11); upk(i11, q11, Q11);
            const float r00r = g00 + y * q00, r00i = -i00 + y * b00;
            const float r01r = g01 + y * q01, r01i = -i01 + y * b01;
            const float r10r = g10 + y * q10, r10i = -i10 + y * b10;
            const float r11r = g11 + y * q11, r11i = -i11 + y * b11;

            // Woodbury: k = r00 - r01*r10/(1+r11)
            const float dr = 1.f + r11r, di = r11i;
            const float dinv = frcp(fmaf(dr, dr, di * di));
            const float qr = r01r * r10r - r01i * r10i;
            const float qi = r01r * r10i + r01i * r10r;
            const float cr2 = (qr * dr + qi * di) * dinv;
            const float ci2 = (qi * dr - qr * di) * dinv;
            const float kr = r00r - cr2, ki = r00i - ci2;

            // scale by 2/(1+omega) = 1 + i*(y/2)
            const float hy = 0.5f * y;
            KF[SK(l0 + 256 * j)] = make_float2(kr - hy * ki, ki + hy * kr);
        }
    }

    if (tid == 0) {
        // analytic Nyquist limit: k_f = Re(sum_n dt*B*C)
        float acc = 0.f;
        #pragma unroll
        for (int n = 0; n < NDIM; n++) acc += s_ny[n];
        KF[SK(LLEN / 2)] = make_float2(acc, 0.f);
    }
    __syncthreads();

    // ---- ifft: three radix-16 passes ---------------------------------------
    // pass 1: stages 0+1 fused with hermitian gather from KF
    {
        const float C8 = 0.92387953251128674f, S8 = 0.38268343236508978f;
        const float CQ = 0.70710678118654752f;
        const float2 W1[4] = {{1.f,0.f},{C8,S8},{CQ,CQ},{S8,C8}};
        const float2 W2[4] = {{1.f,0.f},{CQ,CQ},{0.f,1.f},{-CQ,CQ}};
        const float2 W3[4] = {{1.f,0.f},{S8,C8},{-CQ,CQ},{-C8,-S8}};

        const int J = tid;
        float2 x[16];
        #pragma unroll
        for (int p = 0; p < 4; p++) {
            const int j = 4 * J + p;
            const int br = __brev((unsigned)j) >> 22;                 // 10-bit rev
            const int rj = ((br & 0x155) << 1) | ((br >> 1) & 0x155); // base-4 rev
            const float2 t0 = KF[SK(rj)];
            const float2 t1 = KF[SK(1024 + rj)];
            const float2 c2 = KF[SK(2048 - rj)];  const float2 t2 = make_float2(c2.x, -c2.y);
            const float2 c3 = KF[SK(1024 - rj)];  const float2 t3 = make_float2(c3.x, -c3.y);
            bfly4u(t0, t1, t2, t3, x[4 * p], x[4 * p + 1], x[4 * p + 2], x[4 * p + 3]);
        }
        #pragma unroll
        for (int k = 0; k < 4; k++)
            bfly4(x[k], x[k + 4], x[k + 8], x[k + 12], W1[k], W2[k], W3[k]);
        #pragma unroll
        for (int u = 0; u < 16; u++) X[IX(16 * J + u)] = x[u];
    }
    __syncthreads();

    // pass 2: stages 2+3 on {256B + r + 16t}
    {
        const int B = tid >> 4, r = tid & 15;
        const int eb = 256 * B + r;
        float2 x[16];
        #pragma unroll
        for (int t = 0; t < 16; t++) x[t] = X[IX(eb + 16 * t)];

        {
            const float2 w1 = TW[IX(64 * r)];
            const float2 w2 = cmul(w1, w1);
            const float2 w3 = cmul(w1, w2);
            #pragma unroll
            for (int p = 0; p < 4; p++)
                bfly4(x[4 * p], x[4 * p + 1], x[4 * p + 2], x[4 * p + 3], w1, w2, w3);
        }
        #pragma unroll
        for (int t0 = 0; t0 < 4; t0++) {
            const float2 w1 = TW[IX(16 * (r + 16 * t0))];
            const float2 w2 = cmul(w1, w1);
            const float2 w3 = cmul(w1, w2);
            bfly4(x[t0], x[t0 + 4], x[t0 + 8], x[t0 + 12], w1, w2, w3);
        }
        #pragma unroll
        for (int t = 0; t < 16; t++) X[IX(eb + 16 * t)] = x[t];
    }
    __syncthreads();

    // pass 3: stages 4+5 on {r3 + 256t}, fused real-part store
    {
        const int r3 = tid;
        float2 x[16];
        #pragma unroll
        for (int t = 0; t < 16; t++) x[t] = X[IX(r3 + 256 * t)];

        {
            const float2 w1 = TW[IX(4 * r3)];
            const float2 w2 = cmul(w1, w1);
            const float2 w3 = cmul(w1, w2);
            #pragma unroll
            for (int p = 0; p < 4; p++)
                bfly4(x[4 * p], x[4 * p + 1], x[4 * p + 2], x[4 * p + 3], w1, w2, w3);
        }
        const float scale = 1.0f / (float)LLEN;
        float* o = out + h * LLEN;
        #pragma unroll
        for (int t0 = 0; t0 < 4; t0++) {
            const int k = r3 + 256 * t0;
            const float2 w1 = TW[IX(k)];
            const float2 w2 = cmul(w1, w1);
            const float2 w3 = cmul(w1, w2);
            const float2 t0v = x[t0];
            const float2 t1 = cmul(x[t0 + 4],  w1);
            const float2 t2 = cmul(x[t0 + 8],  w2);
            const float2 t3 = cmul(x[t0 + 12], w3);
            const float ax = t0v.x + t2.x;
            const float bx = t0v.x - t2.x;
            const float cx = t1.x + t3.x;
            const float dx = -(t1.y - t3.y);
            o[k]        = (ax + cx) * scale;
            o[k + 1024] = (bx + dx) * scale;
            o[k + 2048] = (ax - cx) * scale;
            o[k + 3072] = (bx - dx) * scale;
        }
    }
}

extern "C" void kernel_launch(void* const* d_in, const int* in_sizes, int n_in,
                              void* d_out, int out_size) {
    const float* w_re   = (const float*)d_in[0];
    const float* w_im   = (const float*)d_in[1];
    const float* p_re   = (const float*)d_in[2];
    const float* p_im   = (const float*)d_in[3];
    const float* B_re   = (const float*)d_in[4];
    const float* B_im   = (const float*)d_in[5];
    const float* C_re   = (const float*)d_in[6];
    const float* C_im   = (const float*)d_in[7];
    const float* log_dt = (const float*)d_in[8];
    float* out = (float*)d_out;

    const int smem_bytes = SMEM_F2_TOTAL * sizeof(float2);   // 57472 B
    cudaFuncSetAttribute(fused_kernel,
                         cudaFuncAttributeMaxDynamicSharedMemorySize, smem_bytes);
    fused_kernel<<<HDIM, 256, smem_bytes>>>(w_re, w_im, p_re, p_im,
                                            B_re, B_im, C_re, C_im, log_dt, out);
}

// round 16
// speedup vs baseline: 1.2083x; 1.2083x over previous
#include <cuda_runtime.h>
#include <cuda_bf16.h>
#include <math.h>

#define HDIM 512
#define NDIM 32
#define LLEN 4096
#define LF   2049   // LLEN/2 + 1

// ---------------- packed f32x2 + fast-rcp helpers ---------------------------
typedef unsigned long long u64;
__device__ __forceinline__ u64 pk(float lo, float hi) {
    u64 r; asm("mov.b64 %0,{%1,%2};" : "=l"(r) : "f"(lo), "f"(hi)); return r;
}
__device__ __forceinline__ void upk(float& lo, float& hi, u64 v) {
    asm("mov.b64 {%0,%1},%2;" : "=f"(lo), "=f"(hi) : "l"(v));
}
__device__ __forceinline__ u64 f2add(u64 a, u64 b) {
    u64 d; asm("add.rn.f32x2 %0,%1,%2;" : "=l"(d) : "l"(a), "l"(b)); return d;
}
__device__ __forceinline__ u64 f2mul(u64 a, u64 b) {
    u64 d; asm("mul.rn.f32x2 %0,%1,%2;" : "=l"(d) : "l"(a), "l"(b)); return d;
}
__device__ __forceinline__ u64 f2fma(u64 a, u64 b, u64 c) {
    u64 d; asm("fma.rn.f32x2 %0,%1,%2,%3;" : "=l"(d) : "l"(a), "l"(b), "l"(c)); return d;
}
__device__ __forceinline__ float frcp(float x) {        // single MUFU.RCP
    float r; asm("rcp.approx.f32 %0,%1;" : "=f"(r) : "f"(x)); return r;
}

#define IX(i) ((i) ^ (((i) >> 4) & 15))   // X / TW swizzle
#define SK(i) ((i) ^ (((i) >> 4) & 15))   // KF swizzle (range < 2064)

__device__ __forceinline__ float2 cmul(float2 a, float2 b) {
    return make_float2(a.x * b.x - a.y * b.y, a.x * b.y + a.y * b.x);
}
__device__ __forceinline__ void bfly4(float2& x0, float2& x1, float2& x2, float2& x3,
                                      float2 w1, float2 w2, float2 w3) {
    const float2 t0 = x0, t1 = cmul(x1, w1), t2 = cmul(x2, w2), t3 = cmul(x3, w3);
    const float ax = t0.x + t2.x, ay = t0.y + t2.y;
    const float bx = t0.x - t2.x, by = t0.y - t2.y;
    const float cx = t1.x + t3.x, cy = t1.y + t3.y;
    const float dx = -(t1.y - t3.y), dy = t1.x - t3.x;
    x0 = make_float2(ax + cx, ay + cy);
    x1 = make_float2(bx + dx, by + dy);
    x2 = make_float2(ax - cx, ay - cy);
    x3 = make_float2(bx - dx, by - dy);
}
__device__ __forceinline__ void bfly4u(float2 t0, float2 t1, float2 t2, float2 t3,
                                       float2& y0, float2& y1, float2& y2, float2& y3) {
    const float ax = t0.x + t2.x, ay = t0.y + t2.y;
    const float bx = t0.x - t2.x, by = t0.y - t2.y;
    const float cx = t1.x + t3.x, cy = t1.y + t3.y;
    const float dx = -(t1.y - t3.y), dy = t1.x - t3.x;
    y0 = make_float2(ax + cx, ay + cy);
    y1 = make_float2(bx + dx, by + dy);
    y2 = make_float2(ax - cx, ay - cy);
    y3 = make_float2(bx - dx, by - dy);
}

// dynamic smem layout (float2 units): X[0..4095], TW[4096..5119], KF[5120..7183]
#define SMEM_F2_TOTAL 7184

__global__ void __launch_bounds__(256) fused_kernel(
                              const float* __restrict__ w_re, const float* __restrict__ w_im,
                              const float* __restrict__ p_re, const float* __restrict__ p_im,
                              const float* __restrict__ B_re, const float* __restrict__ B_im,
                              const float* __restrict__ C_re, const float* __restrict__ C_im,
                              const float* __restrict__ log_dt,
                              float* __restrict__ out) {
    extern __shared__ float2 smem[];
    float2* X  = smem;            // IX swizzled
    float2* TW = smem + 4096;     // IX swizzled
    float2* KF = smem + 5120;     // SK swizzled

    __shared__ u64 s_MM[NDIM], s_cc[NDIM];
    __shared__ u64 s_ab0[NDIM], s_ab1[NDIM], s_ab2[NDIM], s_ab3[NDIM];
    __shared__ float s_ny[NDIM];

    const int h   = blockIdx.x;
    const int tid = threadIdx.x;

    // ---- twiddle table (W^j = e^{+2*pi*i*j/4096}) --------------------------
    #pragma unroll
    for (int q = 0; q < 4; q++) {
        const int j = tid + 256 * q;
        float s, c;
        sincosf((float)j * (float)(2.0 * M_PI / (double)LLEN), &s, &c);
        TW[IX(j)] = make_float2(c, s);
    }

    // ---- per-head tables ---------------------------------------------------
    const float dt = expf(log_dt[h]);
    if (tid < NDIM) {
        const int idx = h * NDIM + tid;
        const float wr = w_re[idx] * dt, wi = w_im[idx] * dt;
        const float M = wr * wr + wi * wi, c = -2.0f * wr;
        s_MM[tid] = pk(M, M);
        s_cc[tid] = pk(c, c);
        const float br = B_re[idx], bi = B_im[idx];
        const float cr = C_re[idx], ci = C_im[idx];
        const float pr = p_re[idx], pi = p_im[idx];
        const float v00r = dt * (br * cr - bi * ci), v00i = dt * (br * ci + bi * cr);
        const float v01r = dt * (br * pr + bi * pi), v01i = dt * (bi * pr - br * pi);
        const float v10r = dt * (pr * cr - pi * ci), v10i = dt * (pr * ci + pi * cr);
        const float v11r = dt * (pr * pr + pi * pi);
        s_ab0[tid] = pk(-2.f * (v00r * wr + v00i * wi), 2.f * v00r);
        s_ab1[tid] = pk(-2.f * (v01r * wr + v01i * wi), 2.f * v01r);
        s_ab2[tid] = pk(-2.f * (v10r * wr + v10i * wi), 2.f * v10r);
        s_ab3[tid] = pk(-2.f * (v11r * wr),             2.f * v11r);
        s_ny[tid]  = v00r;
    }
    __syncthreads();

    // ---- cauchy phase: two chunks of 4 l-values each (R14 arrangement,
    //      n-loop unroll raised 2 -> 4 for more independent prologue chains) --
    #pragma unroll 1
    for (int cch = 0; cch < 2; cch++) {
        const int l0 = cch * 1024 + tid;   // l = l0 + {0,256,512,768}

        float yv[4];
        #pragma unroll
        for (int j = 0; j < 4; j++)
            yv[j] = 2.0f * tanf((float)(l0 + 256 * j) * (float)(M_PI / (double)LLEN));
        u64 yP[2], ny2P[2];
        #pragma unroll
        for (int jp = 0; jp < 2; jp++) {
            yP[jp]   = pk(yv[2 * jp], yv[2 * jp + 1]);
            ny2P[jp] = pk(-yv[2 * jp] * yv[2 * jp], -yv[2 * jp + 1] * yv[2 * jp + 1]);
        }

        u64 a1_00[4] = {0,0,0,0}, a2_00[4] = {0,0,0,0};
        u64 a1_01[4] = {0,0,0,0}, a2_01[4] = {0,0,0,0};
        u64 a1_10[4] = {0,0,0,0}, a2_10[4] = {0,0,0,0};
        u64 a1_11[4] = {0,0,0,0}, a2_11[4] = {0,0,0,0};

        #pragma unroll 4
        for (int n = 0; n < NDIM; n++) {
            const u64 MM = s_MM[n], cc = s_cc[n];
            const u64 ab0 = s_ab0[n], ab1 = s_ab1[n], ab2 = s_ab2[n], ab3 = s_ab3[n];
            #pragma unroll
            for (int jp = 0; jp < 2; jp++) {
                const u64 DrP  = f2add(MM, ny2P[jp]);
                const u64 DiP  = f2mul(cc, yP[jp]);
                const u64 denP = f2fma(DiP, DiP, f2mul(DrP, DrP));
                float de0, de1; upk(de0, de1, denP);
                const u64 invP = pk(frcp(de0), frcp(de1));
                const u64 grP  = f2mul(DrP, invP);
                const u64 hP   = f2mul(DiP, invP);      // h = -gi
                float gr0, gr1; upk(gr0, gr1, grP);
                float h0,  h1;  upk(h0,  h1,  hP);
                const u64 ggA = pk(gr0, gr0), ggB = pk(gr1, gr1);
                const u64 hhA = pk(h0, h0),   hhB = pk(h1, h1);
                const int ja = 2 * jp, jb = 2 * jp + 1;
                a1_00[ja] = f2fma(ab0, ggA, a1_00[ja]);  a2_00[ja] = f2fma(ab0, hhA, a2_00[ja]);
                a1_01[ja] = f2fma(ab1, ggA, a1_01[ja]);  a2_01[ja] = f2fma(ab1, hhA, a2_01[ja]);
                a1_10[ja] = f2fma(ab2, ggA, a1_10[ja]);  a2_10[ja] = f2fma(ab2, hhA, a2_10[ja]);
                a1_11[ja] = f2fma(ab3, ggA, a1_11[ja]);  a2_11[ja] = f2fma(ab3, hhA, a2_11[ja]);
                a1_00[jb] = f2fma(ab0, ggB, a1_00[jb]);  a2_00[jb] = f2fma(ab0, hhB, a2_00[jb]);
                a1_01[jb] = f2fma(ab1, ggB, a1_01[jb]);  a2_01[jb] = f2fma(ab1, hhB, a2_01[jb]);
                a1_10[jb] = f2fma(ab2, ggB, a1_10[jb]);  a2_10[jb] = f2fma(ab2, hhB, a2_10[jb]);
                a1_11[jb] = f2fma(ab3, ggB, a1_11[jb]);  a2_11[jb] = f2fma(ab3, hhB, a2_11[jb]);
            }
        }

        #pragma unroll
        for (int j = 0; j < 4; j++) {
            const float y = yv[j];
            // a1 lanes = (Sum a*gr, Sum b*gr); a2 lanes = (Sum a*h, Sum b*h)
            float g00, b00, i00, q00; upk(g00, b00, a1_00[j]); upk(i00, q00, a2_00[j]);
            float g01, b01, i01, q01; upk(g01, b01, a1_01[j]); upk(i01, q01, a2_01[j]);
            float g10, b10, i10, q10; upk(g10, b10, a1_10[j]); upk(i10, q10, a2_10[j]);
            float g11, b11, i11, q11; upk(g11, b11, a1_11[j]); upk(i11, q11, a2_11[j]);
            const float r00r = g00 + y * q00, r00i = -i00 + y * b00;
            const float r01r = g01 + y * q01, r01i = -i01 + y * b01;
            const float r10r = g10 + y * q10, r10i = -i10 + y * b10;
            const float r11r = g11 + y * q11, r11i = -i11 + y * b11;

            // Woodbury: k = r00 - r01*r10/(1+r11)
            const float dr = 1.f + r11r, di = r11i;
            const float dinv = frcp(fmaf(dr, dr, di * di));
            const float qr = r01r * r10r - r01i * r10i;
            const float qi = r01r * r10i + r01i * r10r;
            const float cr2 = (qr * dr + qi * di) * dinv;
            const float ci2 = (qi * dr - qr * di) * dinv;
            const float kr = r00r - cr2, ki = r00i - ci2;

            // scale by 2/(1+omega) = 1 + i*(y/2)
            const float hy = 0.5f * y;
            KF[SK(l0 + 256 * j)] = make_float2(kr - hy * ki, ki + hy * kr);
        }
    }

    if (tid == 0) {
        // analytic Nyquist limit: k_f = Re(sum_n dt*B*C)
        float acc = 0.f;
        #pragma unroll
        for (int n = 0; n < NDIM; n++) acc += s_ny[n];
        KF[SK(LLEN / 2)] = make_float2(acc, 0.f);
    }
    __syncthreads();

    // ---- ifft: three radix-16 passes ---------------------------------------
    // pass 1: stages 0+1 fused with hermitian gather from KF
    {
        const float C8 = 0.92387953251128674f, S8 = 0.38268343236508978f;
        const float CQ = 0.70710678118654752f;
        const float2 W1[4] = {{1.f,0.f},{C8,S8},{CQ,CQ},{S8,C8}};
        const float2 W2[4] = {{1.f,0.f},{CQ,CQ},{0.f,1.f},{-CQ,CQ}};
        const float2 W3[4] = {{1.f,0.f},{S8,C8},{-CQ,CQ},{-C8,-S8}};

        const int J = tid;
        float2 x[16];
        #pragma unroll
        for (int p = 0; p < 4; p++) {
            const int j = 4 * J + p;
            const int br = __brev((unsigned)j) >> 22;                 // 10-bit rev
            const int rj = ((br & 0x155) << 1) | ((br >> 1) & 0x155); // base-4 rev
            const float2 t0 = KF[SK(rj)];
            const float2 t1 = KF[SK(1024 + rj)];
            const float2 c2 = KF[SK(2048 - rj)];  const float2 t2 = make_float2(c2.x, -c2.y);
            const float2 c3 = KF[SK(1024 - rj)];  const float2 t3 = make_float2(c3.x, -c3.y);
            bfly4u(t0, t1, t2, t3, x[4 * p], x[4 * p + 1], x[4 * p + 2], x[4 * p + 3]);
        }
        #pragma unroll
        for (int k = 0; k < 4; k++)
            bfly4(x[k], x[k + 4], x[k + 8], x[k + 12], W1[k], W2[k], W3[k]);
        #pragma unroll
        for (int u = 0; u < 16; u++) X[IX(16 * J + u)] = x[u];
    }
    __syncthreads();

    // pass 2: stages 2+3 on {256B + r + 16t}
    {
        const int B = tid >> 4, r = tid & 15;
        const int eb = 256 * B + r;
        float2 x[16];
        #pragma unroll
        for (int t = 0; t < 16; t++) x[t] = X[IX(eb + 16 * t)];

        {
            const float2 w1 = TW[IX(64 * r)];
            const float2 w2 = cmul(w1, w1);
            const float2 w3 = cmul(w1, w2);
            #pragma unroll
            for (int p = 0; p < 4; p++)
                bfly4(x[4 * p], x[4 * p + 1], x[4 * p + 2], x[4 * p + 3], w1, w2, w3);
        }
        #pragma unroll
        for (int t0 = 0; t0 < 4; t0++) {
            const float2 w1 = TW[IX(16 * (r + 16 * t0))];
            const float2 w2 = cmul(w1, w1);
            const float2 w3 = cmul(w1, w2);
            bfly4(x[t0], x[t0 + 4], x[t0 + 8], x[t0 + 12], w1, w2, w3);
        }
        #pragma unroll
        for (int t = 0; t < 16; t++) X[IX(eb + 16 * t)] = x[t];
    }
    __syncthreads();

    // pass 3: stages 4+5 on {r3 + 256t}, fused real-part store
    {
        const int r3 = tid;
        float2 x[16];
        #pragma unroll
        for (int t = 0; t < 16; t++) x[t] = X[IX(r3 + 256 * t)];

        {
            const float2 w1 = TW[IX(4 * r3)];
            const float2 w2 = cmul(w1, w1);
            const float2 w3 = cmul(w1, w2);
            #pragma unroll
            for (int p = 0; p < 4; p++)
                bfly4(x[4 * p], x[4 * p + 1], x[4 * p + 2], x[4 * p + 3], w1, w2, w3);
        }
        const float scale = 1.0f / (float)LLEN;
        float* o = out + h * LLEN;
        #pragma unroll
        for (int t0 = 0; t0 < 4; t0++) {
            const int k = r3 + 256 * t0;
            const float2 w1 = TW[IX(k)];
            const float2 w2 = cmul(w1, w1);
            const float2 w3 = cmul(w1, w2);
            const float2 t0v = x[t0];
            const float2 t1 = cmul(x[t0 + 4],  w1);
            const float2 t2 = cmul(x[t0 + 8],  w2);
            const float2 t3 = cmul(x[t0 + 12], w3);
            const float ax = t0v.x + t2.x;
            const float bx = t0v.x - t2.x;
            const float cx = t1.x + t3.x;
            const float dx = -(t1.y - t3.y);
            o[k]        = (ax + cx) * scale;
            o[k + 1024] = (bx + dx) * scale;
            o[k + 2048] = (ax - cx) * scale;
            o[k + 3072] = (bx - dx) * scale;
        }
    }
}

extern "C" void kernel_launch(void* const* d_in, const int* in_sizes, int n_in,
                              void* d_out, int out_size) {
    const float* w_re   = (const float*)d_in[0];
    const float* w_im   = (const float*)d_in[1];
    const float* p_re   = (const float*)d_in[2];
    const float* p_im   = (const float*)d_in[3];
    const float* B_re   = (const float*)d_in[4];
    const float* B_im   = (const float*)d_in[5];
    const float* C_re   = (const float*)d_in[6];
    const float* C_im   = (const float*)d_in[7];
    const float* log_dt = (const float*)d_in[8];
    float* out = (float*)d_out;

    const int smem_bytes = SMEM_F2_TOTAL * sizeof(float2);   // 57472 B
    cudaFuncSetAttribute(fused_kernel,
                         cudaFuncAttributeMaxDynamicSharedMemorySize, smem_bytes);
    fused_kernel<<<HDIM, 256, smem_bytes>>>(w_re, w_im, p_re, p_im,
                                            B_re, B_im, C_re, C_im, log_dt, out);
}

// round 17
// speedup vs baseline: 1.2600x; 1.0428x over previous
#include <cuda_runtime.h>
#include <cuda_bf16.h>
#include <math.h>

#define HDIM 512
#define NDIM 32
#define LLEN 4096
#define LF   2049   // LLEN/2 + 1

// ---------------- packed f32x2 + fast-rcp helpers ---------------------------
typedef unsigned long long u64;
__device__ __forceinline__ u64 pk(float lo, float hi) {
    u64 r; asm("mov.b64 %0,{%1,%2};" : "=l"(r) : "f"(lo), "f"(hi)); return r;
}
__device__ __forceinline__ void upk(float& lo, float& hi, u64 v) {
    asm("mov.b64 {%0,%1},%2;" : "=f"(lo), "=f"(hi) : "l"(v));
}
__device__ __forceinline__ u64 f2add(u64 a, u64 b) {
    u64 d; asm("add.rn.f32x2 %0,%1,%2;" : "=l"(d) : "l"(a), "l"(b)); return d;
}
__device__ __forceinline__ u64 f2mul(u64 a, u64 b) {
    u64 d; asm("mul.rn.f32x2 %0,%1,%2;" : "=l"(d) : "l"(a), "l"(b)); return d;
}
__device__ __forceinline__ u64 f2fma(u64 a, u64 b, u64 c) {
    u64 d; asm("fma.rn.f32x2 %0,%1,%2,%3;" : "=l"(d) : "l"(a), "l"(b), "l"(c)); return d;
}
__device__ __forceinline__ float frcp(float x) {        // single MUFU.RCP
    float r; asm("rcp.approx.f32 %0,%1;" : "=f"(r) : "f"(x)); return r;
}

#define IX(i) ((i) ^ (((i) >> 4) & 15))   // X / TW swizzle
#define SK(i) ((i) ^ (((i) >> 4) & 15))   // KF swizzle (range < 2064)

__device__ __forceinline__ float2 cmul(float2 a, float2 b) {
    return make_float2(a.x * b.x - a.y * b.y, a.x * b.y + a.y * b.x);
}
__device__ __forceinline__ void bfly4(float2& x0, float2& x1, float2& x2, float2& x3,
                                      float2 w1, float2 w2, float2 w3) {
    const float2 t0 = x0, t1 = cmul(x1, w1), t2 = cmul(x2, w2), t3 = cmul(x3, w3);
    const float ax = t0.x + t2.x, ay = t0.y + t2.y;
    const float bx = t0.x - t2.x, by = t0.y - t2.y;
    const float cx = t1.x + t3.x, cy = t1.y + t3.y;
    const float dx = -(t1.y - t3.y), dy = t1.x - t3.x;
    x0 = make_float2(ax + cx, ay + cy);
    x1 = make_float2(bx + dx, by + dy);
    x2 = make_float2(ax - cx, ay - cy);
    x3 = make_float2(bx - dx, by - dy);
}
__device__ __forceinline__ void bfly4u(float2 t0, float2 t1, float2 t2, float2 t3,
                                       float2& y0, float2& y1, float2& y2, float2& y3) {
    const float ax = t0.x + t2.x, ay = t0.y + t2.y;
    const float bx = t0.x - t2.x, by = t0.y - t2.y;
    const float cx = t1.x + t3.x, cy = t1.y + t3.y;
    const float dx = -(t1.y - t3.y), dy = t1.x - t3.x;
    y0 = make_float2(ax + cx, ay + cy);
    y1 = make_float2(bx + dx, by + dy);
    y2 = make_float2(ax - cx, ay - cy);
    y3 = make_float2(bx - dx, by - dy);
}

// dynamic smem layout (float2 units): X[0..4095], TW[4096..5119], KF[5120..7183]
#define SMEM_F2_TOTAL 7184

__global__ void __launch_bounds__(256) fused_kernel(
                              const float* __restrict__ w_re, const float* __restrict__ w_im,
                              const float* __restrict__ p_re, const float* __restrict__ p_im,
                              const float* __restrict__ B_re, const float* __restrict__ B_im,
                              const float* __restrict__ C_re, const float* __restrict__ C_im,
                              const float* __restrict__ log_dt,
                              float* __restrict__ out) {
    extern __shared__ float2 smem[];
    float2* X  = smem;            // IX swizzled
    float2* TW = smem + 4096;     // IX swizzled
    float2* KF = smem + 5120;     // SK swizzled

    __shared__ u64 s_MM[NDIM], s_cc[NDIM];
    __shared__ u64 s_ab0[NDIM], s_ab1[NDIM], s_ab2[NDIM], s_ab3[NDIM];
    __shared__ float s_ny[NDIM];
    __shared__ float2 s_co[33], s_fi[32];   // split twiddle tables

    const int h   = blockIdx.x;
    const int tid = threadIdx.x;

    // ---- phase A: small tables (disjoint warps, parallel) ------------------
    if (tid >= 128 && tid < 161) {          // coarse: e^{2*pi*i*32k/4096}, k<=32
        const int k = tid - 128;
        float s, c;
        sincosf((float)k * (float)(2.0 * M_PI * 32.0 / (double)LLEN), &s, &c);
        s_co[k] = make_float2(c, s);
    }
    if (tid >= 192 && tid < 224) {          // fine: e^{2*pi*i*j/4096}, j<32
        const int j = tid - 192;
        float s, c;
        sincosf((float)j * (float)(2.0 * M_PI / (double)LLEN), &s, &c);
        s_fi[j] = make_float2(c, s);
    }
    if (tid < NDIM) {                       // per-head cauchy tables
        const float dt = expf(log_dt[h]);
        const int idx = h * NDIM + tid;
        const float wr = w_re[idx] * dt, wi = w_im[idx] * dt;
        const float M = wr * wr + wi * wi, c = -2.0f * wr;
        s_MM[tid] = pk(M, M);
        s_cc[tid] = pk(c, c);
        const float br = B_re[idx], bi = B_im[idx];
        const float cr = C_re[idx], ci = C_im[idx];
        const float pr = p_re[idx], pi = p_im[idx];
        const float v00r = dt * (br * cr - bi * ci), v00i = dt * (br * ci + bi * cr);
        const float v01r = dt * (br * pr + bi * pi), v01i = dt * (bi * pr - br * pi);
        const float v10r = dt * (pr * cr - pi * ci), v10i = dt * (pr * ci + pi * cr);
        const float v11r = dt * (pr * pr + pi * pi);
        s_ab0[tid] = pk(-2.f * (v00r * wr + v00i * wi), 2.f * v00r);
        s_ab1[tid] = pk(-2.f * (v01r * wr + v01i * wi), 2.f * v01r);
        s_ab2[tid] = pk(-2.f * (v10r * wr + v10i * wi), 2.f * v10r);
        s_ab3[tid] = pk(-2.f * (v11r * wr),             2.f * v11r);
        s_ny[tid]  = v00r;
    }
    __syncthreads();

    // ---- phase B: TW fill from split tables (read by FFT after next barrier)
    #pragma unroll
    for (int q = 0; q < 4; q++) {
        const int j = tid + 256 * q;
        TW[IX(j)] = cmul(s_co[j >> 5], s_fi[j & 31]);
    }

    // ---- cauchy phase: two chunks of 4 l-values each ------------------------
    #pragma unroll 1
    for (int cch = 0; cch < 2; cch++) {
        const int l0 = cch * 1024 + tid;   // l = l0 + {0,256,512,768}

        // y = 2*tan(pi*l/4096) from split tables, cancellation-free
        float yv[4];
        if (cch == 0) {
            #pragma unroll
            for (int j = 0; j < 4; j++) {
                const int idx = l0 + 256 * j;              // < 1024
                const float2 t = cmul(s_co[idx >> 5], s_fi[idx & 31]);
                yv[j] = 2.0f * t.y * frcp(1.0f + t.x);
            }
        } else {
            #pragma unroll
            for (int j = 0; j < 4; j++) {
                const int m = 2048 - (l0 + 256 * j);       // in [1, 1024]
                const float2 t = cmul(s_co[m >> 5], s_fi[m & 31]);
                yv[j] = 2.0f * (1.0f + t.x) * frcp(t.y);
            }
        }
        u64 yP[2], ny2P[2];
        #pragma unroll
        for (int jp = 0; jp < 2; jp++) {
            yP[jp]   = pk(yv[2 * jp], yv[2 * jp + 1]);
            ny2P[jp] = pk(-yv[2 * jp] * yv[2 * jp], -yv[2 * jp + 1] * yv[2 * jp + 1]);
        }

        u64 a1_00[4] = {0,0,0,0}, a2_00[4] = {0,0,0,0};
        u64 a1_01[4] = {0,0,0,0}, a2_01[4] = {0,0,0,0};
        u64 a1_10[4] = {0,0,0,0}, a2_10[4] = {0,0,0,0};
        u64 a1_11[4] = {0,0,0,0}, a2_11[4] = {0,0,0,0};

        #pragma unroll 4
        for (int n = 0; n < NDIM; n++) {
            const u64 MM = s_MM[n], cc = s_cc[n];
            const u64 ab0 = s_ab0[n], ab1 = s_ab1[n], ab2 = s_ab2[n], ab3 = s_ab3[n];
            #pragma unroll
            for (int jp = 0; jp < 2; jp++) {
                const u64 DrP  = f2add(MM, ny2P[jp]);
                const u64 DiP  = f2mul(cc, yP[jp]);
                const u64 denP = f2fma(DiP, DiP, f2mul(DrP, DrP));
                float de0, de1; upk(de0, de1, denP);
                const u64 invP = pk(frcp(de0), frcp(de1));
                const u64 grP  = f2mul(DrP, invP);
                const u64 hP   = f2mul(DiP, invP);      // h = -gi
                float gr0, gr1; upk(gr0, gr1, grP);
                float h0,  h1;  upk(h0,  h1,  hP);
                const u64 ggA = pk(gr0, gr0), ggB = pk(gr1, gr1);
                const u64 hhA = pk(h0, h0),   hhB = pk(h1, h1);
                const int ja = 2 * jp, jb = 2 * jp + 1;
                a1_00[ja] = f2fma(ab0, ggA, a1_00[ja]);  a2_00[ja] = f2fma(ab0, hhA, a2_00[ja]);
                a1_01[ja] = f2fma(ab1, ggA, a1_01[ja]);  a2_01[ja] = f2fma(ab1, hhA, a2_01[ja]);
                a1_10[ja] = f2fma(ab2, ggA, a1_10[ja]);  a2_10[ja] = f2fma(ab2, hhA, a2_10[ja]);
                a1_11[ja] = f2fma(ab3, ggA, a1_11[ja]);  a2_11[ja] = f2fma(ab3, hhA, a2_11[ja]);
                a1_00[jb] = f2fma(ab0, ggB, a1_00[jb]);  a2_00[jb] = f2fma(ab0, hhB, a2_00[jb]);
                a1_01[jb] = f2fma(ab1, ggB, a1_01[jb]);  a2_01[jb] = f2fma(ab1, hhB, a2_01[jb]);
                a1_10[jb] = f2fma(ab2, ggB, a1_10[jb]);  a2_10[jb] = f2fma(ab2, hhB, a2_10[jb]);
                a1_11[jb] = f2fma(ab3, ggB, a1_11[jb]);  a2_11[jb] = f2fma(ab3, hhB, a2_11[jb]);
            }
        }

        #pragma unroll
        for (int j = 0; j < 4; j++) {
            const float y = yv[j];
            float g00, b00, i00, q00; upk(g00, b00, a1_00[j]); upk(i00, q00, a2_00[j]);
            float g01, b01, i01, q01; upk(g01, b01, a1_01[j]); upk(i01, q01, a2_01[j]);
            float g10, b10, i10, q10; upk(g10, b10, a1_10[j]); upk(i10, q10, a2_10[j]);
            float g11, b11, i11, q11; upk(g11, b11, a1_11[j]); upk(i11, q11, a2_11[j]);
            const float r00r = g00 + y * q00, r00i = -i00 + y * b00;
            const float r01r = g01 + y * q01, r01i = -i01 + y * b01;
            const float r10r = g10 + y * q10, r10i = -i10 + y * b10;
            const float r11r = g11 + y * q11, r11i = -i11 + y * b11;

            // Woodbury: k = r00 - r01*r10/(1+r11)
            const float dr = 1.f + r11r, di = r11i;
            const float dinv = frcp(fmaf(dr, dr, di * di));
            const float qr = r01r * r10r - r01i * r10i;
            const float qi = r01r * r10i + r01i * r10r;
            const float cr2 = (qr * dr + qi * di) * dinv;
            const float ci2 = (qi * dr - qr * di) * dinv;
            const float kr = r00r - cr2, ki = r00i - ci2;

            // scale by 2/(1+omega) = 1 + i*(y/2)
            const float hy = 0.5f * y;
            KF[SK(l0 + 256 * j)] = make_float2(kr - hy * ki, ki + hy * kr);
        }
    }

    if (tid == 0) {
        // analytic Nyquist limit: k_f = Re(sum_n dt*B*C)
        float acc = 0.f;
        #pragma unroll
        for (int n = 0; n < NDIM; n++) acc += s_ny[n];
        KF[SK(LLEN / 2)] = make_float2(acc, 0.f);
    }
    __syncthreads();

    // ---- ifft: three radix-16 passes ---------------------------------------
    // pass 1: stages 0+1 fused with hermitian gather from KF
    {
        const float C8 = 0.92387953251128674f, S8 = 0.38268343236508978f;
        const float CQ = 0.70710678118654752f;
        const float2 W1[4] = {{1.f,0.f},{C8,S8},{CQ,CQ},{S8,C8}};
        const float2 W2[4] = {{1.f,0.f},{CQ,CQ},{0.f,1.f},{-CQ,CQ}};
        const float2 W3[4] = {{1.f,0.f},{S8,C8},{-CQ,CQ},{-C8,-S8}};

        const int J = tid;
        float2 x[16];
        #pragma unroll
        for (int p = 0; p < 4; p++) {
            const int j = 4 * J + p;
            const int br = __brev((unsigned)j) >> 22;                 // 10-bit rev
            const int rj = ((br & 0x155) << 1) | ((br >> 1) & 0x155); // base-4 rev
            const float2 t0 = KF[SK(rj)];
            const float2 t1 = KF[SK(1024 + rj)];
            const float2 c2 = KF[SK(2048 - rj)];  const float2 t2 = make_float2(c2.x, -c2.y);
            const float2 c3 = KF[SK(1024 - rj)];  const float2 t3 = make_float2(c3.x, -c3.y);
            bfly4u(t0, t1, t2, t3, x[4 * p], x[4 * p + 1], x[4 * p + 2], x[4 * p + 3]);
        }
        #pragma unroll
        for (int k = 0; k < 4; k++)
            bfly4(x[k], x[k + 4], x[k + 8], x[k + 12], W1[k], W2[k], W3[k]);
        #pragma unroll
        for (int u = 0; u < 16; u++) X[IX(16 * J + u)] = x[u];
    }
    __syncthreads();

    // pass 2: stages 2+3 on {256B + r + 16t}
    {
        const int B = tid >> 4, r = tid & 15;
        const int eb = 256 * B + r;
        float2 x[16];
        #pragma unroll
        for (int t = 0; t < 16; t++) x[t] = X[IX(eb + 16 * t)];

        {
            const float2 w1 = TW[IX(64 * r)];
            const float2 w2 = cmul(w1, w1);
            const float2 w3 = cmul(w1, w2);
            #pragma unroll
            for (int p = 0; p < 4; p++)
                bfly4(x[4 * p], x[4 * p + 1], x[4 * p + 2], x[4 * p + 3], w1, w2, w3);
        }
        #pragma unroll
        for (int t0 = 0; t0 < 4; t0++) {
            const float2 w1 = TW[IX(16 * (r + 16 * t0))];
            const float2 w2 = cmul(w1, w1);
            const float2 w3 = cmul(w1, w2);
            bfly4(x[t0], x[t0 + 4], x[t0 + 8], x[t0 + 12], w1, w2, w3);
        }
        #pragma unroll
        for (int t = 0; t < 16; t++) X[IX(eb + 16 * t)] = x[t];
    }
    __syncthreads();

    // pass 3: stages 4+5 on {r3 + 256t}, fused real-part store
    {
        const int r3 = tid;
        float2 x[16];
        #pragma unroll
        for (int t = 0; t < 16; t++) x[t] = X[IX(r3 + 256 * t)];

        {
            const float2 w1 = TW[IX(4 * r3)];
            const float2 w2 = cmul(w1, w1);
            const float2 w3 = cmul(w1, w2);
            #pragma unroll
            for (int p = 0; p < 4; p++)
                bfly4(x[4 * p], x[4 * p + 1], x[4 * p + 2], x[4 * p + 3], w1, w2, w3);
        }
        const float scale = 1.0f / (float)LLEN;
        float* o = out + h * LLEN;
        #pragma unroll
        for (int t0 = 0; t0 < 4; t0++) {
            const int k = r3 + 256 * t0;
            const float2 w1 = TW[IX(k)];
            const float2 w2 = cmul(w1, w1);
            const float2 w3 = cmul(w1, w2);
            const float2 t0v = x[t0];
            const float2 t1 = cmul(x[t0 + 4],  w1);
            const float2 t2 = cmul(x[t0 + 8],  w2);
            const float2 t3 = cmul(x[t0 + 12], w3);
            const float ax = t0v.x + t2.x;
            const float bx = t0v.x - t2.x;
            const float cx = t1.x + t3.x;
            const float dx = -(t1.y - t3.y);
            o[k]        = (ax + cx) * scale;
            o[k + 1024] = (bx + dx) * scale;
            o[k + 2048] = (ax - cx) * scale;
            o[k + 3072] = (bx - dx) * scale;
        }
    }
}

extern "C" void kernel_launch(void* const* d_in, const int* in_sizes, int n_in,
                              void* d_out, int out_size) {
    const float* w_re   = (const float*)d_in[0];
    const float* w_im   = (const float*)d_in[1];
    const float* p_re   = (const float*)d_in[2];
    const float* p_im   = (const float*)d_in[3];
    const float* B_re   = (const float*)d_in[4];
    const float* B_im   = (const float*)d_in[5];
    const float* C_re   = (const float*)d_in[6];
    const float* C_im   = (const float*)d_in[7];
    const float* log_dt = (const float*)d_in[8];
    float* out = (float*)d_out;

    const int smem_bytes = SMEM_F2_TOTAL * sizeof(float2);   // 57472 B
    cudaFuncSetAttribute(fused_kernel,
                         cudaFuncAttributeMaxDynamicSharedMemorySize, smem_bytes);
    fused_kernel<<<HDIM, 256, smem_bytes>>>(w_re, w_im, p_re, p_im,
                                            B_re, B_im, C_re, C_im, log_dt, out);
}